// round 4
// baseline (speedup 1.0000x reference)
#include <cuda_runtime.h>
#include <cuda_bf16.h>
#include <cstdint>

// ---------------- problem constants ----------------
#define BATCH 256
#define TSEQ  2048
#define SOBS  39
#define AACT  4
#define HID   256
#define EPS   1e-5f

#define TILE_M   128
#define NTILES   (BATCH * TSEQ / TILE_M)   // 4096
#define TPB      (TSEQ / TILE_M)           // 16 tiles per batch
#define GRID     148
#define THREADS  256                        // 8 warps, warp owns 16 rows

#define PITCH    264                        // bf16 elems per weight row (bank stagger)

// ---------------- global weight image (prep kernel fills) ----------------
__device__ __align__(16) __nv_bfloat16 g_w1h[48 * PITCH];
__device__ __align__(16) __nv_bfloat16 g_w1l[48 * PITCH];
__device__ __align__(16) __nv_bfloat16 g_w2h[256 * PITCH];
__device__ __align__(16) __nv_bfloat16 g_w2l[256 * PITCH];
__device__ float g_partials[NTILES];

// ---------------- smem byte offsets ----------------
#define W1H_OFF   0          // 48*264*2 = 25344
#define W1L_OFF   25344      // 25344
#define W2B_OFF   50688      // 2 bufs * (hi 8448 + lo 8448) = 33792
#define A2H_OFF   84480      // 65536   (xs[128][44] f32 = 22528 aliases here)
#define A2L_OFF   150016     // 65536
#define VEC_OFF   215552     // 7 * 1024
#define BSUM_OFF  222720     // 32
#define SMEM_DYN  223776     // + align slack

// ---------------- PTX helpers ----------------
__device__ __forceinline__ uint32_t smem_u32(const void* p) {
    uint32_t a;
    asm("{ .reg .u64 t; cvta.to.shared.u64 t, %1; cvt.u32.u64 %0, t; }" : "=r"(a) : "l"(p));
    return a;
}
__device__ __forceinline__ void cpa16(uint32_t dst, const void* src) {
    uint64_t g; asm("cvta.to.global.u64 %0, %1;" : "=l"(g) : "l"(src));
    asm volatile("cp.async.cg.shared.global [%0], [%1], 16;" :: "r"(dst), "l"(g) : "memory");
}
#define CP_COMMIT() asm volatile("cp.async.commit_group;" ::: "memory")
#define CP_WAIT(n)  asm volatile("cp.async.wait_group %0;" :: "n"(n) : "memory")

__device__ __forceinline__ void ldsm4t(uint32_t& r0, uint32_t& r1, uint32_t& r2, uint32_t& r3,
                                       uint32_t addr) {
    asm volatile("ldmatrix.sync.aligned.m8n8.x4.trans.shared.b16 {%0,%1,%2,%3}, [%4];"
                 : "=r"(r0), "=r"(r1), "=r"(r2), "=r"(r3) : "r"(addr));
}
__device__ __forceinline__ void mma16816(float* c, const uint32_t* a, uint32_t b0, uint32_t b1) {
    asm volatile(
        "mma.sync.aligned.m16n8k16.row.col.f32.bf16.bf16.f32 "
        "{%0,%1,%2,%3}, {%4,%5,%6,%7}, {%8,%9}, {%0,%1,%2,%3};"
        : "+f"(c[0]), "+f"(c[1]), "+f"(c[2]), "+f"(c[3])
        : "r"(a[0]), "r"(a[1]), "r"(a[2]), "r"(a[3]), "r"(b0), "r"(b1));
}
__device__ __forceinline__ uint32_t pack_bf16x2(float lo, float hi) {
    uint32_t r;
    asm("cvt.rn.bf16x2.f32 %0, %1, %2;" : "=r"(r) : "f"(hi), "f"(lo));  // d<31:16>=hi, d<15:0>=lo
    return r;
}
__device__ __forceinline__ void split2(float vx, float vy, uint32_t& h, uint32_t& l) {
    h = pack_bf16x2(vx, vy);
    float hx = __bfloat162float(__ushort_as_bfloat16((unsigned short)(h & 0xffffu)));
    float hy = __bfloat162float(__ushort_as_bfloat16((unsigned short)(h >> 16)));
    l = pack_bf16x2(vx - hx, vy - hy);
}
__device__ __forceinline__ float warp_sum(float v) {
    #pragma unroll
    for (int off = 16; off; off >>= 1) v += __shfl_xor_sync(0xffffffffu, v, off);
    return v;
}
__device__ __forceinline__ float quad_sum(float v) {   // reduce across lane%4 group
    v += __shfl_xor_sync(0xffffffffu, v, 1);
    v += __shfl_xor_sync(0xffffffffu, v, 2);
    return v;
}

// ---------------- prep: split + transpose-pad weights into [k][PITCH] image ----------------
__global__ void prep_kernel(const float* __restrict__ W1, const float* __restrict__ W2)
{
    int idx = blockIdx.x * blockDim.x + threadIdx.x;
    const int TOT = (48 + 256) * PITCH;
    if (idx >= TOT) return;
    int row = idx / PITCH, col = idx % PITCH;
    float v = 0.f;
    if (row < 48) { if (row < 43 && col < 256) v = W1[row * 256 + col]; }
    else          { int k = row - 48; if (col < 256) v = W2[k * 256 + col]; }
    __nv_bfloat16 h = __float2bfloat16(v);
    __nv_bfloat16 l = __float2bfloat16(v - __bfloat162float(h));
    if (row < 48) { g_w1h[idx] = h; g_w1l[idx] = l; }
    else          { int j = (row - 48) * PITCH + col; g_w2h[j] = h; g_w2l[j] = l; }
}

// ---------------- main fused kernel ----------------
__global__ __launch_bounds__(THREADS, 1)
void fused_mma_kernel(const float* __restrict__ obs, const float* __restrict__ act,
                      const float* __restrict__ b1,  const float* __restrict__ g1,
                      const float* __restrict__ be1, const float* __restrict__ b2,
                      const float* __restrict__ g2,  const float* __restrict__ be2,
                      const float* __restrict__ W3)
{
    extern __shared__ char raw[];
    char* sm = (char*)((((uintptr_t)raw) + 127) & ~(uintptr_t)127);
    const uint32_t sbase = smem_u32(sm);
    const int tid = threadIdx.x, warp = tid >> 5, lane = tid & 31;
    const int qr = lane >> 2;            // 0..7
    const int qc = (lane & 3) << 1;      // 0,2,4,6

    float* xs   = (float*)(sm + A2H_OFF);          // [128][44], aliases A2H
    float* b1s  = (float*)(sm + VEC_OFF);
    float* g1s  = b1s + 256;  float* be1s = g1s + 256;
    float* b2s  = be1s + 256; float* g2s  = b2s + 256; float* be2s = g2s + 256;
    float* w3s  = be2s + 256;
    float* bsum = (float*)(sm + BSUM_OFF);

    // vectors
    b1s[tid] = b1[tid]; g1s[tid] = g1[tid]; be1s[tid] = be1[tid];
    b2s[tid] = b2[tid]; g2s[tid] = g2[tid]; be2s[tid] = be2[tid];
    w3s[tid] = W3[tid];

    // W1 (both planes) resident in SMEM
    for (int i = tid; i < 1584; i += THREADS)
        cpa16(sbase + W1H_OFF + i * 16, (const char*)g_w1h + i * 16);
    for (int i = tid; i < 1584; i += THREADS)
        cpa16(sbase + W1L_OFF + i * 16, (const char*)g_w1l + i * 16);
    CP_COMMIT();
    CP_WAIT(0);
    __syncthreads();

    // ldmatrix per-lane address component (k row within 16, n8 sub-block)
    const uint32_t lrow = (uint32_t)(lane & 15);
    const uint32_t lcol = (uint32_t)((lane >> 4) << 3);
    const uint32_t ldsm_off = (lrow * PITCH + lcol) * 2;

    for (int tile = blockIdx.x; tile < NTILES; tile += gridDim.x) {
        const long long g0 = (long long)tile * TILE_M;

        // ---- issue W2 chunks 0,1 (cp.async double buffer prime) ----
        #pragma unroll
        for (int pc = 0; pc < 2; pc++) {
            uint32_t dh = sbase + W2B_OFF + pc * 16896;
            const __nv_bfloat16* sh = g_w2h + pc * 16 * PITCH;
            const __nv_bfloat16* sl = g_w2l + pc * 16 * PITCH;
            for (int i = tid; i < 528; i += THREADS) {
                cpa16(dh + i * 16,        (const char*)sh + i * 16);
                cpa16(dh + 8448 + i * 16, (const char*)sl + i * 16);
            }
            CP_COMMIT();
        }

        // ---- stage x tile into xs ----
        {
            const float* ob = obs + g0 * SOBS;
            for (int i = tid; i < TILE_M * SOBS; i += THREADS) {
                int r = i / SOBS, d = i - SOBS * r;
                xs[r * 44 + d] = ob[i];
            }
            const float* ac = act + g0 * AACT;
            for (int i = tid; i < TILE_M * AACT; i += THREADS)
                xs[(i >> 2) * 44 + SOBS + (i & 3)] = ac[i];
            if (tid < TILE_M) xs[tid * 44 + 43] = 0.f;
        }
        __syncthreads();

        // ---- build GEMM1 A fragments from xs (regs) ----
        uint32_t a1h[3][4], a1l[3][4];
        {
            const int r  = warp * 16 + qr;
            const int r8 = r + 8;
            #pragma unroll
            for (int kk = 0; kk < 3; kk++) {
                int c0 = kk * 16 + qc;
                int c8 = c0 + 8;
                float2 x00 = *(const float2*)&xs[r  * 44 + c0];
                float2 x10 = *(const float2*)&xs[r8 * 44 + c0];
                float2 x01 = make_float2(0.f, 0.f), x11 = make_float2(0.f, 0.f);
                if (c8 < 44) {
                    x01 = *(const float2*)&xs[r  * 44 + c8];
                    x11 = *(const float2*)&xs[r8 * 44 + c8];
                }
                split2(x00.x, x00.y, a1h[kk][0], a1l[kk][0]);
                split2(x10.x, x10.y, a1h[kk][1], a1l[kk][1]);
                split2(x01.x, x01.y, a1h[kk][2], a1l[kk][2]);
                split2(x11.x, x11.y, a1h[kk][3], a1l[kk][3]);
            }
        }
        __syncthreads();   // all xs reads done before LN1 overwrites A2H region

        // ---- GEMM1: c = x @ W1  (3 split products), K=48 ----
        float c[32][4];
        #pragma unroll
        for (int nf = 0; nf < 32; nf++)
            { c[nf][0] = 0.f; c[nf][1] = 0.f; c[nf][2] = 0.f; c[nf][3] = 0.f; }

        #pragma unroll
        for (int kk = 0; kk < 3; kk++) {
            uint32_t bh_base = sbase + W1H_OFF + kk * 8448 + ldsm_off;
            uint32_t bl_base = sbase + W1L_OFF + kk * 8448 + ldsm_off;
            #pragma unroll 4
            for (int nf2 = 0; nf2 < 16; nf2++) {
                uint32_t h0, h1, h2, h3, l0, l1, l2, l3;
                ldsm4t(h0, h1, h2, h3, bh_base + nf2 * 32);
                ldsm4t(l0, l1, l2, l3, bl_base + nf2 * 32);
                mma16816(c[2*nf2],   a1h[kk], h0, h1);
                mma16816(c[2*nf2+1], a1h[kk], h2, h3);
                mma16816(c[2*nf2],   a1h[kk], l0, l1);
                mma16816(c[2*nf2+1], a1h[kk], l2, l3);
                mma16816(c[2*nf2],   a1l[kk], h0, h1);
                mma16816(c[2*nf2+1], a1l[kk], h2, h3);
            }
        }

        // ---- LN1 + ReLU -> pack into GEMM2 A fragments -> SMEM ----
        {
            float sA = 0.f, qA = 0.f, sB = 0.f, qB = 0.f;
            #pragma unroll
            for (int nf = 0; nf < 32; nf++) {
                float2 bb = *(const float2*)&b1s[nf * 8 + qc];
                c[nf][0] += bb.x; c[nf][1] += bb.y; c[nf][2] += bb.x; c[nf][3] += bb.y;
                sA += c[nf][0] + c[nf][1];
                qA = fmaf(c[nf][0], c[nf][0], qA); qA = fmaf(c[nf][1], c[nf][1], qA);
                sB += c[nf][2] + c[nf][3];
                qB = fmaf(c[nf][2], c[nf][2], qB); qB = fmaf(c[nf][3], c[nf][3], qB);
            }
            sA = quad_sum(sA); qA = quad_sum(qA); sB = quad_sum(sB); qB = quad_sum(qB);
            float muA = sA * (1.f / HID), muB = sB * (1.f / HID);
            float vA = qA * (1.f / HID) - muA * muA + EPS;
            float vB = qB * (1.f / HID) - muB * muB + EPS;
            float rsA = rsqrtf(vA); rsA = rsA * (1.5f - 0.5f * vA * rsA * rsA);
            float rsB = rsqrtf(vB); rsB = rsB * (1.5f - 0.5f * vB * rsB * rsB);
            #pragma unroll
            for (int nf = 0; nf < 32; nf++) {
                float2 gg = *(const float2*)&g1s[nf * 8 + qc];
                float2 ee = *(const float2*)&be1s[nf * 8 + qc];
                float v0 = fmaxf((c[nf][0] - muA) * rsA * gg.x + ee.x, 0.f);
                float v1 = fmaxf((c[nf][1] - muA) * rsA * gg.y + ee.y, 0.f);
                float v2 = fmaxf((c[nf][2] - muB) * rsB * gg.x + ee.x, 0.f);
                float v3 = fmaxf((c[nf][3] - muB) * rsB * gg.y + ee.y, 0.f);
                uint32_t h01, l01, h23, l23;
                split2(v0, v1, h01, l01);
                split2(v2, v3, h23, l23);
                c[nf][0] = __uint_as_float(h01); c[nf][1] = __uint_as_float(h23);
                c[nf][2] = __uint_as_float(l01); c[nf][3] = __uint_as_float(l23);
            }
            #pragma unroll
            for (int kk = 0; kk < 16; kk++) {
                uint32_t slot = (uint32_t)(((warp * 16 + kk) * 32 + lane) * 16);
                *(uint4*)(sm + A2H_OFF + slot) = make_uint4(
                    __float_as_uint(c[2*kk][0]), __float_as_uint(c[2*kk][1]),
                    __float_as_uint(c[2*kk+1][0]), __float_as_uint(c[2*kk+1][1]));
                *(uint4*)(sm + A2L_OFF + slot) = make_uint4(
                    __float_as_uint(c[2*kk][2]), __float_as_uint(c[2*kk][3]),
                    __float_as_uint(c[2*kk+1][2]), __float_as_uint(c[2*kk+1][3]));
            }
        }

        // ---- GEMM2: c = h1 @ W2, 16 k-chunks streamed through double buffer ----
        #pragma unroll
        for (int nf = 0; nf < 32; nf++)
            { c[nf][0] = 0.f; c[nf][1] = 0.f; c[nf][2] = 0.f; c[nf][3] = 0.f; }

        for (int ck = 0; ck < 16; ++ck) {
            if (ck < 15) { CP_WAIT(1); } else { CP_WAIT(0); }
            __syncthreads();

            uint32_t slot = (uint32_t)(((warp * 16 + ck) * 32 + lane) * 16);
            uint4 ah4 = *(const uint4*)(sm + A2H_OFF + slot);
            uint4 al4 = *(const uint4*)(sm + A2L_OFF + slot);
            uint32_t a2h[4] = {ah4.x, ah4.y, ah4.z, ah4.w};
            uint32_t a2l[4] = {al4.x, al4.y, al4.z, al4.w};

            uint32_t bh_base = sbase + W2B_OFF + (ck & 1) * 16896 + ldsm_off;
            uint32_t bl_base = bh_base + 8448;
            #pragma unroll 4
            for (int nf2 = 0; nf2 < 16; nf2++) {
                uint32_t h0, h1, h2, h3, l0, l1, l2, l3;
                ldsm4t(h0, h1, h2, h3, bh_base + nf2 * 32);
                ldsm4t(l0, l1, l2, l3, bl_base + nf2 * 32);
                mma16816(c[2*nf2],   a2h, h0, h1);
                mma16816(c[2*nf2+1], a2h, h2, h3);
                mma16816(c[2*nf2],   a2h, l0, l1);
                mma16816(c[2*nf2+1], a2h, l2, l3);
                mma16816(c[2*nf2],   a2l, h0, h1);
                mma16816(c[2*nf2+1], a2l, h2, h3);
            }
            __syncthreads();

            if (ck + 2 < 16) {
                uint32_t dh = sbase + W2B_OFF + (ck & 1) * 16896;
                const __nv_bfloat16* sh = g_w2h + (ck + 2) * 16 * PITCH;
                const __nv_bfloat16* sl = g_w2l + (ck + 2) * 16 * PITCH;
                for (int i = tid; i < 528; i += THREADS) {
                    cpa16(dh + i * 16,        (const char*)sh + i * 16);
                    cpa16(dh + 8448 + i * 16, (const char*)sl + i * 16);
                }
                CP_COMMIT();
            }
        }

        // ---- LN2 + ReLU + dot(W3) ----
        float rp = 0.f;
        {
            float sA = 0.f, qA = 0.f, sB = 0.f, qB = 0.f;
            #pragma unroll
            for (int nf = 0; nf < 32; nf++) {
                float2 bb = *(const float2*)&b2s[nf * 8 + qc];
                c[nf][0] += bb.x; c[nf][1] += bb.y; c[nf][2] += bb.x; c[nf][3] += bb.y;
                sA += c[nf][0] + c[nf][1];
                qA = fmaf(c[nf][0], c[nf][0], qA); qA = fmaf(c[nf][1], c[nf][1], qA);
                sB += c[nf][2] + c[nf][3];
                qB = fmaf(c[nf][2], c[nf][2], qB); qB = fmaf(c[nf][3], c[nf][3], qB);
            }
            sA = quad_sum(sA); qA = quad_sum(qA); sB = quad_sum(sB); qB = quad_sum(qB);
            float muA = sA * (1.f / HID), muB = sB * (1.f / HID);
            float vA = qA * (1.f / HID) - muA * muA + EPS;
            float vB = qB * (1.f / HID) - muB * muB + EPS;
            float rsA = rsqrtf(vA); rsA = rsA * (1.5f - 0.5f * vA * rsA * rsA);
            float rsB = rsqrtf(vB); rsB = rsB * (1.5f - 0.5f * vB * rsB * rsB);
            #pragma unroll
            for (int nf = 0; nf < 32; nf++) {
                float2 gg = *(const float2*)&g2s[nf * 8 + qc];
                float2 ee = *(const float2*)&be2s[nf * 8 + qc];
                float2 ww = *(const float2*)&w3s[nf * 8 + qc];
                float v0 = fmaxf((c[nf][0] - muA) * rsA * gg.x + ee.x, 0.f);
                float v1 = fmaxf((c[nf][1] - muA) * rsA * gg.y + ee.y, 0.f);
                float v2 = fmaxf((c[nf][2] - muB) * rsB * gg.x + ee.x, 0.f);
                float v3 = fmaxf((c[nf][3] - muB) * rsB * gg.y + ee.y, 0.f);
                rp = fmaf(v0, ww.x, rp); rp = fmaf(v1, ww.y, rp);
                rp = fmaf(v2, ww.x, rp); rp = fmaf(v3, ww.y, rp);
            }
        }
        float rtot = warp_sum(rp);
        if (lane == 0) bsum[warp] = rtot;
        __syncthreads();
        if (tid == 0) {
            float t = 0.f;
            #pragma unroll
            for (int w = 0; w < 8; w++) t += bsum[w];
            g_partials[tile] = t;
        }
        __syncthreads();
    }
}

// ---------------- deterministic final reduction ----------------
__global__ void reduce_kernel(const float* __restrict__ b3, float* __restrict__ out)
{
    const int b = threadIdx.x;             // 256 threads, one batch each
    float t = (float)TSEQ * b3[0];
    #pragma unroll
    for (int i = 0; i < TPB; i++) t += g_partials[b * TPB + i];
    out[b] = t;
}

extern "C" void kernel_launch(void* const* d_in, const int* in_sizes, int n_in,
                              void* d_out, int out_size)
{
    const float* obs = (const float*)d_in[0];
    const float* act = (const float*)d_in[1];
    const float* W1  = (const float*)d_in[2];
    const float* b1  = (const float*)d_in[3];
    const float* g1  = (const float*)d_in[4];
    const float* be1 = (const float*)d_in[5];
    const float* W2  = (const float*)d_in[6];
    const float* b2  = (const float*)d_in[7];
    const float* g2  = (const float*)d_in[8];
    const float* be2 = (const float*)d_in[9];
    const float* W3  = (const float*)d_in[10];
    const float* b3  = (const float*)d_in[11];

    prep_kernel<<<((48 + 256) * PITCH + 255) / 256, 256>>>(W1, W2);

    cudaFuncSetAttribute(fused_mma_kernel,
                         cudaFuncAttributeMaxDynamicSharedMemorySize, SMEM_DYN);
    fused_mma_kernel<<<GRID, THREADS, SMEM_DYN>>>(obs, act, b1, g1, be1, b2, g2, be2, W3);

    reduce_kernel<<<1, BATCH>>>(b3, (float*)d_out);
}

// round 5
// speedup vs baseline: 1.0495x; 1.0495x over previous
#include <cuda_runtime.h>
#include <cuda_bf16.h>
#include <cstdint>

// ---------------- problem constants ----------------
#define BATCH 256
#define TSEQ  2048
#define SOBS  39
#define AACT  4
#define HID   256
#define EPS   1e-5f

#define TILE_M   128
#define NTILES   (BATCH * TSEQ / TILE_M)   // 4096
#define TPB      (TSEQ / TILE_M)           // 16 tiles per batch
#define GRID     148
#define THREADS  512                        // 16 warps; warp = (rowgroup, nhalf)

#define PITCH    264                        // bf16 elems per weight row (bank stagger)

// ---------------- global weight image (prep kernel fills) ----------------
__device__ __align__(16) __nv_bfloat16 g_w1h[48 * PITCH];
__device__ __align__(16) __nv_bfloat16 g_w1l[48 * PITCH];
__device__ __align__(16) __nv_bfloat16 g_w2h[256 * PITCH];
__device__ __align__(16) __nv_bfloat16 g_w2l[256 * PITCH];
__device__ float g_partials[NTILES];
__device__ unsigned int g_arrive = 0;

// ---------------- smem byte offsets ----------------
#define W1H_OFF   0          // 25344
#define W1L_OFF   25344      // 25344
#define W2B_OFF   50688      // 2 bufs * (hi 8448 + lo 8448) = 33792
#define A2H_OFF   84480      // 65536   (xs[128][44] f32 = 22528 aliases here)
#define A2L_OFF   150016     // 65536
#define VEC_OFF   215552     // 7 * 1024
#define LNX_OFF   222720     // 8 grp * 2 half * 8 qr * 16B = 2048
#define BSUM_OFF  224768     // 16 floats
#define FLAG_OFF  224832     // 4
#define SMEM_DYN  224960     // incl. align slack

// ---------------- PTX helpers ----------------
__device__ __forceinline__ uint32_t smem_u32(const void* p) {
    uint32_t a;
    asm("{ .reg .u64 t; cvta.to.shared.u64 t, %1; cvt.u32.u64 %0, t; }" : "=r"(a) : "l"(p));
    return a;
}
__device__ __forceinline__ void cpa16(uint32_t dst, const void* src) {
    uint64_t g; asm("cvta.to.global.u64 %0, %1;" : "=l"(g) : "l"(src));
    asm volatile("cp.async.cg.shared.global [%0], [%1], 16;" :: "r"(dst), "l"(g) : "memory");
}
#define CP_COMMIT() asm volatile("cp.async.commit_group;" ::: "memory")
#define CP_WAIT(n)  asm volatile("cp.async.wait_group %0;" :: "n"(n) : "memory")

__device__ __forceinline__ void ldsm4t(uint32_t& r0, uint32_t& r1, uint32_t& r2, uint32_t& r3,
                                       uint32_t addr) {
    asm volatile("ldmatrix.sync.aligned.m8n8.x4.trans.shared.b16 {%0,%1,%2,%3}, [%4];"
                 : "=r"(r0), "=r"(r1), "=r"(r2), "=r"(r3) : "r"(addr));
}
__device__ __forceinline__ void mma16816(float* c, const uint32_t* a, uint32_t b0, uint32_t b1) {
    asm volatile(
        "mma.sync.aligned.m16n8k16.row.col.f32.bf16.bf16.f32 "
        "{%0,%1,%2,%3}, {%4,%5,%6,%7}, {%8,%9}, {%0,%1,%2,%3};"
        : "+f"(c[0]), "+f"(c[1]), "+f"(c[2]), "+f"(c[3])
        : "r"(a[0]), "r"(a[1]), "r"(a[2]), "r"(a[3]), "r"(b0), "r"(b1));
}
__device__ __forceinline__ uint32_t pack_bf16x2(float lo, float hi) {
    uint32_t r;
    asm("cvt.rn.bf16x2.f32 %0, %1, %2;" : "=r"(r) : "f"(hi), "f"(lo));
    return r;
}
__device__ __forceinline__ void split2(float vx, float vy, uint32_t& h, uint32_t& l) {
    h = pack_bf16x2(vx, vy);
    float hx = __bfloat162float(__ushort_as_bfloat16((unsigned short)(h & 0xffffu)));
    float hy = __bfloat162float(__ushort_as_bfloat16((unsigned short)(h >> 16)));
    l = pack_bf16x2(vx - hx, vy - hy);
}
__device__ __forceinline__ float warp_sum(float v) {
    #pragma unroll
    for (int off = 16; off; off >>= 1) v += __shfl_xor_sync(0xffffffffu, v, off);
    return v;
}
__device__ __forceinline__ float quad_sum(float v) {
    v += __shfl_xor_sync(0xffffffffu, v, 1);
    v += __shfl_xor_sync(0xffffffffu, v, 2);
    return v;
}

// ---------------- prep: split + transpose-pad weights into [k][PITCH] image ----------------
__global__ void prep_kernel(const float* __restrict__ W1, const float* __restrict__ W2)
{
    int idx = blockIdx.x * blockDim.x + threadIdx.x;
    const int TOT = (48 + 256) * PITCH;
    if (idx >= TOT) return;
    int row = idx / PITCH, col = idx % PITCH;
    float v = 0.f;
    if (row < 48) { if (row < 43 && col < 256) v = W1[row * 256 + col]; }
    else          { int k = row - 48; if (col < 256) v = W2[k * 256 + col]; }
    __nv_bfloat16 h = __float2bfloat16(v);
    __nv_bfloat16 l = __float2bfloat16(v - __bfloat162float(h));
    if (row < 48) { g_w1h[idx] = h; g_w1l[idx] = l; }
    else          { int j = (row - 48) * PITCH + col; g_w2h[j] = h; g_w2l[j] = l; }
}

// ---------------- main fused kernel ----------------
__global__ __launch_bounds__(THREADS, 1)
void fused_mma_kernel(const float* __restrict__ obs, const float* __restrict__ act,
                      const float* __restrict__ b1,  const float* __restrict__ g1,
                      const float* __restrict__ be1, const float* __restrict__ b2,
                      const float* __restrict__ g2,  const float* __restrict__ be2,
                      const float* __restrict__ W3,  const float* __restrict__ b3,
                      float* __restrict__ out)
{
    extern __shared__ char raw[];
    char* sm = (char*)((((uintptr_t)raw) + 127) & ~(uintptr_t)127);
    const uint32_t sbase = smem_u32(sm);
    const int tid = threadIdx.x, warp = tid >> 5, lane = tid & 31;
    const int grp = warp >> 1;              // 0..7 : rows grp*16..+15
    const int nhalf = warp & 1;             // 0/1 : cols nhalf*128..+127
    const int qr = lane >> 2;               // 0..7
    const int qc = (lane & 3) << 1;         // 0,2,4,6
    const int ncol0 = nhalf * 128;          // warp's first output column

    float* xs   = (float*)(sm + A2H_OFF);   // [128][44], aliases A2H
    float* b1s  = (float*)(sm + VEC_OFF);
    float* g1s  = b1s + 256;  float* be1s = g1s + 256;
    float* b2s  = be1s + 256; float* g2s  = b2s + 256; float* be2s = g2s + 256;
    float* w3s  = be2s + 256;
    float* lnx  = (float*)(sm + LNX_OFF);   // [8][2][8][4]
    float* bsum = (float*)(sm + BSUM_OFF);
    unsigned int* flag = (unsigned int*)(sm + FLAG_OFF);

    if (tid < 256) {
        b1s[tid] = b1[tid]; g1s[tid] = g1[tid]; be1s[tid] = be1[tid];
        b2s[tid] = b2[tid]; g2s[tid] = g2[tid]; be2s[tid] = be2[tid];
        w3s[tid] = W3[tid];
    }
    // W1 (both planes) resident in SMEM, once per CTA
    for (int i = tid; i < 1584; i += THREADS) {
        cpa16(sbase + W1H_OFF + i * 16, (const char*)g_w1h + i * 16);
        cpa16(sbase + W1L_OFF + i * 16, (const char*)g_w1l + i * 16);
    }
    CP_COMMIT();
    CP_WAIT(0);
    __syncthreads();

    // ldmatrix per-lane address component
    const uint32_t lrow = (uint32_t)(lane & 15);
    const uint32_t lcol = (uint32_t)((lane >> 4) << 3);
    const uint32_t ldsm_off = (lrow * PITCH + lcol) * 2 + (uint32_t)nhalf * 256;

    for (int tile = blockIdx.x; tile < NTILES; tile += GRID) {
        const long long g0 = (long long)tile * TILE_M;

        // ---- prime W2 chunks 0,1 ----
        #pragma unroll
        for (int pc = 0; pc < 2; pc++) {
            uint32_t dh = sbase + W2B_OFF + pc * 16896;
            const __nv_bfloat16* sh = g_w2h + pc * 16 * PITCH;
            const __nv_bfloat16* sl = g_w2l + pc * 16 * PITCH;
            for (int i = tid; i < 528; i += THREADS) {
                cpa16(dh + i * 16,        (const char*)sh + i * 16);
                cpa16(dh + 8448 + i * 16, (const char*)sl + i * 16);
            }
            CP_COMMIT();
        }

        // ---- stage x tile into xs ----
        {
            const float* ob = obs + g0 * SOBS;
            for (int i = tid; i < TILE_M * SOBS; i += THREADS) {
                int r = i / SOBS, d = i - SOBS * r;
                xs[r * 44 + d] = ob[i];
            }
            const float* ac = act + g0 * AACT;
            for (int i = tid; i < TILE_M * AACT; i += THREADS)
                xs[(i >> 2) * 44 + SOBS + (i & 3)] = ac[i];
            if (tid < TILE_M) xs[tid * 44 + 43] = 0.f;
        }
        __syncthreads();

        // ---- build GEMM1 A fragments (rows grp*16..) ----
        uint32_t a1h[3][4], a1l[3][4];
        {
            const int r  = grp * 16 + qr;
            const int r8 = r + 8;
            #pragma unroll
            for (int kk = 0; kk < 3; kk++) {
                int c0 = kk * 16 + qc;
                int c8 = c0 + 8;
                float2 x00 = *(const float2*)&xs[r  * 44 + c0];
                float2 x10 = *(const float2*)&xs[r8 * 44 + c0];
                float2 x01 = make_float2(0.f, 0.f), x11 = make_float2(0.f, 0.f);
                if (c8 < 44) {
                    x01 = *(const float2*)&xs[r  * 44 + c8];
                    x11 = *(const float2*)&xs[r8 * 44 + c8];
                }
                split2(x00.x, x00.y, a1h[kk][0], a1l[kk][0]);
                split2(x10.x, x10.y, a1h[kk][1], a1l[kk][1]);
                split2(x01.x, x01.y, a1h[kk][2], a1l[kk][2]);
                split2(x11.x, x11.y, a1h[kk][3], a1l[kk][3]);
            }
        }
        __syncthreads();   // xs reads done before LN1 overwrites A2H region

        // ---- GEMM1: c = x @ W1 (3 split products), K=48, N=128 per warp ----
        float c[16][4];
        #pragma unroll
        for (int nf = 0; nf < 16; nf++)
            { c[nf][0] = 0.f; c[nf][1] = 0.f; c[nf][2] = 0.f; c[nf][3] = 0.f; }

        #pragma unroll
        for (int kk = 0; kk < 3; kk++) {
            uint32_t bh_base = sbase + W1H_OFF + kk * 8448 + ldsm_off;
            uint32_t bl_base = bh_base + 25344;   // W1L - W1H
            #pragma unroll 4
            for (int nf2 = 0; nf2 < 8; nf2++) {
                uint32_t h0, h1, h2, h3, l0, l1, l2, l3;
                ldsm4t(h0, h1, h2, h3, bh_base + nf2 * 32);
                ldsm4t(l0, l1, l2, l3, bl_base + nf2 * 32);
                mma16816(c[2*nf2],   a1h[kk], h0, h1);
                mma16816(c[2*nf2+1], a1h[kk], h2, h3);
                mma16816(c[2*nf2],   a1h[kk], l0, l1);
                mma16816(c[2*nf2+1], a1h[kk], l2, l3);
                mma16816(c[2*nf2],   a1l[kk], h0, h1);
                mma16816(c[2*nf2+1], a1l[kk], h2, h3);
            }
        }

        // ---- LN1 (cross-warp-pair stats) + ReLU -> A2 fragments -> SMEM ----
        {
            float sA = 0.f, qA = 0.f, sB = 0.f, qB = 0.f;
            #pragma unroll
            for (int nf = 0; nf < 16; nf++) {
                float2 bb = *(const float2*)&b1s[ncol0 + nf * 8 + qc];
                c[nf][0] += bb.x; c[nf][1] += bb.y; c[nf][2] += bb.x; c[nf][3] += bb.y;
                sA += c[nf][0] + c[nf][1];
                qA = fmaf(c[nf][0], c[nf][0], qA); qA = fmaf(c[nf][1], c[nf][1], qA);
                sB += c[nf][2] + c[nf][3];
                qB = fmaf(c[nf][2], c[nf][2], qB); qB = fmaf(c[nf][3], c[nf][3], qB);
            }
            sA = quad_sum(sA); qA = quad_sum(qA); sB = quad_sum(sB); qB = quad_sum(qB);
            if ((lane & 3) == 0)
                *(float4*)&lnx[((grp * 2 + nhalf) * 8 + qr) * 4] = make_float4(sA, qA, sB, qB);
            __syncthreads();
            {
                float4 o = *(const float4*)&lnx[((grp * 2 + (nhalf ^ 1)) * 8 + qr) * 4];
                sA += o.x; qA += o.y; sB += o.z; qB += o.w;
            }
            float muA = sA * (1.f / HID), muB = sB * (1.f / HID);
            float vA = qA * (1.f / HID) - muA * muA + EPS;
            float vB = qB * (1.f / HID) - muB * muB + EPS;
            float rsA = rsqrtf(vA); rsA = rsA * (1.5f - 0.5f * vA * rsA * rsA);
            float rsB = rsqrtf(vB); rsB = rsB * (1.5f - 0.5f * vB * rsB * rsB);
            #pragma unroll
            for (int nf = 0; nf < 16; nf++) {
                float2 gg = *(const float2*)&g1s[ncol0 + nf * 8 + qc];
                float2 ee = *(const float2*)&be1s[ncol0 + nf * 8 + qc];
                float v0 = fmaxf((c[nf][0] - muA) * rsA * gg.x + ee.x, 0.f);
                float v1 = fmaxf((c[nf][1] - muA) * rsA * gg.y + ee.y, 0.f);
                float v2 = fmaxf((c[nf][2] - muB) * rsB * gg.x + ee.x, 0.f);
                float v3 = fmaxf((c[nf][3] - muB) * rsB * gg.y + ee.y, 0.f);
                uint32_t h01, l01, h23, l23;
                split2(v0, v1, h01, l01);
                split2(v2, v3, h23, l23);
                c[nf][0] = __uint_as_float(h01); c[nf][1] = __uint_as_float(h23);
                c[nf][2] = __uint_as_float(l01); c[nf][3] = __uint_as_float(l23);
            }
            #pragma unroll
            for (int j = 0; j < 8; j++) {
                int ck = nhalf * 8 + j;
                uint32_t slot = (uint32_t)(((grp * 16 + ck) * 32 + lane) * 16);
                *(uint4*)(sm + A2H_OFF + slot) = make_uint4(
                    __float_as_uint(c[2*j][0]), __float_as_uint(c[2*j][1]),
                    __float_as_uint(c[2*j+1][0]), __float_as_uint(c[2*j+1][1]));
                *(uint4*)(sm + A2L_OFF + slot) = make_uint4(
                    __float_as_uint(c[2*j][2]), __float_as_uint(c[2*j][3]),
                    __float_as_uint(c[2*j+1][2]), __float_as_uint(c[2*j+1][3]));
            }
        }

        // ---- GEMM2: c = h1 @ W2, 16 k-chunks, double-buffered ----
        #pragma unroll
        for (int nf = 0; nf < 16; nf++)
            { c[nf][0] = 0.f; c[nf][1] = 0.f; c[nf][2] = 0.f; c[nf][3] = 0.f; }

        for (int ck = 0; ck < 16; ++ck) {
            if (ck < 15) { CP_WAIT(1); } else { CP_WAIT(0); }
            __syncthreads();

            uint32_t slot = (uint32_t)(((grp * 16 + ck) * 32 + lane) * 16);
            uint4 ah4 = *(const uint4*)(sm + A2H_OFF + slot);
            uint4 al4 = *(const uint4*)(sm + A2L_OFF + slot);
            uint32_t a2h[4] = {ah4.x, ah4.y, ah4.z, ah4.w};
            uint32_t a2l[4] = {al4.x, al4.y, al4.z, al4.w};

            uint32_t bh_base = sbase + W2B_OFF + (ck & 1) * 16896 + ldsm_off;
            uint32_t bl_base = bh_base + 8448;
            #pragma unroll 4
            for (int nf2 = 0; nf2 < 8; nf2++) {
                uint32_t h0, h1, h2, h3, l0, l1, l2, l3;
                ldsm4t(h0, h1, h2, h3, bh_base + nf2 * 32);
                ldsm4t(l0, l1, l2, l3, bl_base + nf2 * 32);
                mma16816(c[2*nf2],   a2h, h0, h1);
                mma16816(c[2*nf2+1], a2h, h2, h3);
                mma16816(c[2*nf2],   a2h, l0, l1);
                mma16816(c[2*nf2+1], a2h, l2, l3);
                mma16816(c[2*nf2],   a2l, h0, h1);
                mma16816(c[2*nf2+1], a2l, h2, h3);
            }
            __syncthreads();

            if (ck + 2 < 16) {
                uint32_t dh = sbase + W2B_OFF + (ck & 1) * 16896;
                const __nv_bfloat16* sh = g_w2h + (ck + 2) * 16 * PITCH;
                const __nv_bfloat16* sl = g_w2l + (ck + 2) * 16 * PITCH;
                for (int i = tid; i < 528; i += THREADS) {
                    cpa16(dh + i * 16,        (const char*)sh + i * 16);
                    cpa16(dh + 8448 + i * 16, (const char*)sl + i * 16);
                }
                CP_COMMIT();
            }
        }

        // ---- LN2 (cross-warp-pair stats) + ReLU + dot(W3) ----
        float rp = 0.f;
        {
            float sA = 0.f, qA = 0.f, sB = 0.f, qB = 0.f;
            #pragma unroll
            for (int nf = 0; nf < 16; nf++) {
                float2 bb = *(const float2*)&b2s[ncol0 + nf * 8 + qc];
                c[nf][0] += bb.x; c[nf][1] += bb.y; c[nf][2] += bb.x; c[nf][3] += bb.y;
                sA += c[nf][0] + c[nf][1];
                qA = fmaf(c[nf][0], c[nf][0], qA); qA = fmaf(c[nf][1], c[nf][1], qA);
                sB += c[nf][2] + c[nf][3];
                qB = fmaf(c[nf][2], c[nf][2], qB); qB = fmaf(c[nf][3], c[nf][3], qB);
            }
            sA = quad_sum(sA); qA = quad_sum(qA); sB = quad_sum(sB); qB = quad_sum(qB);
            if ((lane & 3) == 0)
                *(float4*)&lnx[((grp * 2 + nhalf) * 8 + qr) * 4] = make_float4(sA, qA, sB, qB);
            __syncthreads();
            {
                float4 o = *(const float4*)&lnx[((grp * 2 + (nhalf ^ 1)) * 8 + qr) * 4];
                sA += o.x; qA += o.y; sB += o.z; qB += o.w;
            }
            float muA = sA * (1.f / HID), muB = sB * (1.f / HID);
            float vA = qA * (1.f / HID) - muA * muA + EPS;
            float vB = qB * (1.f / HID) - muB * muB + EPS;
            float rsA = rsqrtf(vA); rsA = rsA * (1.5f - 0.5f * vA * rsA * rsA);
            float rsB = rsqrtf(vB); rsB = rsB * (1.5f - 0.5f * vB * rsB * rsB);
            #pragma unroll
            for (int nf = 0; nf < 16; nf++) {
                float2 gg = *(const float2*)&g2s[ncol0 + nf * 8 + qc];
                float2 ee = *(const float2*)&be2s[ncol0 + nf * 8 + qc];
                float2 ww = *(const float2*)&w3s[ncol0 + nf * 8 + qc];
                float v0 = fmaxf((c[nf][0] - muA) * rsA * gg.x + ee.x, 0.f);
                float v1 = fmaxf((c[nf][1] - muA) * rsA * gg.y + ee.y, 0.f);
                float v2 = fmaxf((c[nf][2] - muB) * rsB * gg.x + ee.x, 0.f);
                float v3 = fmaxf((c[nf][3] - muB) * rsB * gg.y + ee.y, 0.f);
                rp = fmaf(v0, ww.x, rp); rp = fmaf(v1, ww.y, rp);
                rp = fmaf(v2, ww.x, rp); rp = fmaf(v3, ww.y, rp);
            }
        }
        float rtot = warp_sum(rp);
        if (lane == 0) bsum[warp] = rtot;
        __syncthreads();
        if (tid == 0) {
            float t = 0.f;
            #pragma unroll
            for (int w = 0; w < 16; w++) t += bsum[w];
            g_partials[tile] = t;
        }
        __syncthreads();
    }

    // ---- last-block deterministic reduction into out[] ----
    __threadfence();
    if (tid == 0) {
        unsigned int old = atomicAdd(&g_arrive, 1u);
        *flag = (old == GRID - 1) ? 1u : 0u;
    }
    __syncthreads();
    if (*flag) {
        __threadfence();
        float bb3 = b3[0];
        for (int b = tid; b < BATCH; b += THREADS) {
            float t = (float)TSEQ * bb3;
            #pragma unroll
            for (int i = 0; i < TPB; i++) t += __ldcg(&g_partials[b * TPB + i]);
            out[b] = t;
        }
        __syncthreads();
        if (tid == 0) { g_arrive = 0; __threadfence(); }
    }
}

extern "C" void kernel_launch(void* const* d_in, const int* in_sizes, int n_in,
                              void* d_out, int out_size)
{
    const float* obs = (const float*)d_in[0];
    const float* act = (const float*)d_in[1];
    const float* W1  = (const float*)d_in[2];
    const float* b1  = (const float*)d_in[3];
    const float* g1  = (const float*)d_in[4];
    const float* be1 = (const float*)d_in[5];
    const float* W2  = (const float*)d_in[6];
    const float* b2  = (const float*)d_in[7];
    const float* g2  = (const float*)d_in[8];
    const float* be2 = (const float*)d_in[9];
    const float* W3  = (const float*)d_in[10];
    const float* b3  = (const float*)d_in[11];

    prep_kernel<<<((48 + 256) * PITCH + 255) / 256, 256>>>(W1, W2);

    cudaFuncSetAttribute(fused_mma_kernel,
                         cudaFuncAttributeMaxDynamicSharedMemorySize, SMEM_DYN);
    fused_mma_kernel<<<GRID, THREADS, SMEM_DYN>>>(obs, act, b1, g1, be1, b2, g2, be2,
                                                  W3, b3, (float*)d_out);
}

// round 6
// speedup vs baseline: 3.5606x; 3.3926x over previous
#include <cuda_runtime.h>
#include <cuda_bf16.h>
#include <cstdint>

// ---------------- problem constants ----------------
#define BATCH 256
#define TSEQ  2048
#define SOBS  39
#define AACT  4
#define HID   256
#define EPS   1e-5f

#define TILE_M  64
#define NTILES  8192                 // BATCH*TSEQ/TILE_M
#define TPB     32                   // tiles per batch
#define GRID    296                  // 2 CTAs per SM
#define THREADS 256                  // 8 warps: mgrp=warp>>2 (m32), ngrp=warp&3 (n64)

#define PITCH   264
#define ROWB    (PITCH*2)            // 528 bytes per k-row
#define PLANE_B (16*ROWB)            // 8448
#define CHUNK_B (2*PLANE_B)          // 16896 (hi plane + lo plane)
#define NCHK    19                   // 3 W1 chunks (k48) + 16 W2 chunks (k256)

// ---------------- global scratch ----------------
__device__ __align__(16) unsigned char g_wimg[NCHK * CHUNK_B];
__device__ float g_partials[NTILES];
__device__ unsigned int g_arrive = 0;

// ---------------- smem byte offsets (from 128-aligned base) ----------------
#define A2H_OFF  0        // 32768 (xs staging [64][39]f32 + [64][4]f32 aliases first 11008B)
#define A2L_OFF  32768    // 32768
#define WBUF_OFF 65536    // 2 slots * 16896 = 33792
#define VEC_OFF  99328    // 7 * 1024
#define LNX_OFF  106496   // 64 rows * 4 ngrp * 2 floats = 2048
#define BSUM_OFF 108544   // 8 floats
#define MBAR_OFF 108576   // full0,full1,empty0,empty1,xsb : 5*8 = 40
#define FLAG_OFF 108616   // 4
#define SMEM_DYN 108928

// ---------------- PTX helpers ----------------
__device__ __forceinline__ uint32_t smem_u32(const void* p) {
    uint32_t a;
    asm("{ .reg .u64 t; cvta.to.shared.u64 t, %1; cvt.u32.u64 %0, t; }" : "=r"(a) : "l"(p));
    return a;
}
#define MBARRIER_INIT(addr, cnt) \
    asm volatile("mbarrier.init.shared.b64 [%0], %1;" :: "r"(addr), "r"(cnt) : "memory")
#define MBARRIER_EXPECT_TX(addr, bytes) \
    asm volatile("mbarrier.arrive.expect_tx.shared.b64 _, [%0], %1;" :: "r"(addr), "r"(bytes) : "memory")
#define MBARRIER_ARRIVE(addr) \
    asm volatile("mbarrier.arrive.shared.b64 _, [%0];" :: "r"(addr) : "memory")

#define MBARRIER_WAIT_PARITY(mbar_addr, phase_parity) do { \
    uint32_t _mbar = (uint32_t)(mbar_addr); \
    uint32_t _par  = (uint32_t)(phase_parity); \
    asm volatile( \
        "{\n\t" \
        ".reg .pred P1;\n\t" \
        "WAIT_LOOP_%=:\n\t" \
        "mbarrier.try_wait.parity.acquire.cta.shared::cta.b64 P1, [%0], %1, 0x989680;\n\t" \
        "@P1 bra.uni WAIT_DONE_%=;\n\t" \
        "bra.uni WAIT_LOOP_%=;\n\t" \
        "WAIT_DONE_%=:\n\t" \
        "}" :: "r"(_mbar), "r"(_par) : "memory"); \
} while (0)

__device__ __forceinline__ void bulk_g2s(uint32_t dst, const void* src, uint32_t bytes, uint32_t mbar) {
    uint64_t gsrc;
    asm("cvta.to.global.u64 %0, %1;" : "=l"(gsrc) : "l"(src));
    asm volatile(
        "cp.async.bulk.shared::cluster.global.mbarrier::complete_tx::bytes [%0], [%1], %2, [%3];"
        :: "r"(dst), "l"(gsrc), "r"(bytes), "r"(mbar) : "memory");
}

__device__ __forceinline__ void ldsm4t(uint32_t& r0, uint32_t& r1, uint32_t& r2, uint32_t& r3,
                                       uint32_t addr) {
    asm volatile("ldmatrix.sync.aligned.m8n8.x4.trans.shared.b16 {%0,%1,%2,%3}, [%4];"
                 : "=r"(r0), "=r"(r1), "=r"(r2), "=r"(r3) : "r"(addr));
}
__device__ __forceinline__ void mma16816(float* c, const uint32_t* a, uint32_t b0, uint32_t b1) {
    asm volatile(
        "mma.sync.aligned.m16n8k16.row.col.f32.bf16.bf16.f32 "
        "{%0,%1,%2,%3}, {%4,%5,%6,%7}, {%8,%9}, {%0,%1,%2,%3};"
        : "+f"(c[0]), "+f"(c[1]), "+f"(c[2]), "+f"(c[3])
        : "r"(a[0]), "r"(a[1]), "r"(a[2]), "r"(a[3]), "r"(b0), "r"(b1));
}
__device__ __forceinline__ uint32_t pack_bf16x2(float lo, float hi) {
    uint32_t r;
    asm("cvt.rn.bf16x2.f32 %0, %1, %2;" : "=r"(r) : "f"(hi), "f"(lo));
    return r;
}
__device__ __forceinline__ void split2(float vx, float vy, uint32_t& h, uint32_t& l) {
    h = pack_bf16x2(vx, vy);
    float hx = __bfloat162float(__ushort_as_bfloat16((unsigned short)(h & 0xffffu)));
    float hy = __bfloat162float(__ushort_as_bfloat16((unsigned short)(h >> 16)));
    l = pack_bf16x2(vx - hx, vy - hy);
}
__device__ __forceinline__ float warp_sum(float v) {
    #pragma unroll
    for (int off = 16; off; off >>= 1) v += __shfl_xor_sync(0xffffffffu, v, off);
    return v;
}
__device__ __forceinline__ float quad_sum(float v) {
    v += __shfl_xor_sync(0xffffffffu, v, 1);
    v += __shfl_xor_sync(0xffffffffu, v, 2);
    return v;
}

// ---------------- prep: split weights into 19-chunk SMEM-image ring ----------------
__global__ void prep_kernel(const float* __restrict__ W1, const float* __restrict__ W2)
{
    int idx = blockIdx.x * blockDim.x + threadIdx.x;
    const int TOT = NCHK * 16 * PITCH;   // 80256
    if (idx >= TOT) return;
    int c = idx / (16 * PITCH);
    int rem = idx - c * 16 * PITCH;
    int r = rem / PITCH, n = rem % PITCH;
    int k = c * 16 + r;
    float v = 0.f;
    if (n < 256) {
        if (c < 3) { if (k < 43) v = W1[k * 256 + n]; }
        else       v = W2[(k - 48) * 256 + n];
    }
    __nv_bfloat16 h = __float2bfloat16(v);
    __nv_bfloat16 l = __float2bfloat16(v - __bfloat162float(h));
    unsigned char* base = g_wimg + c * CHUNK_B + r * ROWB + n * 2;
    *(__nv_bfloat16*)base             = h;
    *(__nv_bfloat16*)(base + PLANE_B) = l;
}

// ---------------- main fused kernel ----------------
__global__ __launch_bounds__(THREADS, 2)
void fused_mma_kernel(const float* __restrict__ obs, const float* __restrict__ act,
                      const float* __restrict__ b1,  const float* __restrict__ g1,
                      const float* __restrict__ be1, const float* __restrict__ b2,
                      const float* __restrict__ g2,  const float* __restrict__ be2,
                      const float* __restrict__ W3,  const float* __restrict__ b3,
                      float* __restrict__ out)
{
    extern __shared__ char raw[];
    char* sm = (char*)((((uintptr_t)raw) + 127) & ~(uintptr_t)127);
    const uint32_t sbase = smem_u32(sm);
    const int tid = threadIdx.x, warp = tid >> 5, lane = tid & 31;
    const int mgrp = warp >> 2;             // 0..1 : rows mgrp*32..+31
    const int ngrp = warp & 3;              // 0..3 : cols ngrp*64..+63
    const int qr = lane >> 2;               // 0..7
    const int qc = (lane & 3) << 1;         // 0,2,4,6

    float* xsO  = (float*)(sm + A2H_OFF);           // [64][39] packed
    float* xsA  = (float*)(sm + A2H_OFF + 9984);    // [64][4]
    float* b1s  = (float*)(sm + VEC_OFF);
    float* g1s  = b1s + 256;  float* be1s = g1s + 256;
    float* b2s  = be1s + 256; float* g2s  = b2s + 256; float* be2s = g2s + 256;
    float* w3s  = be2s + 256;
    float* lnx  = (float*)(sm + LNX_OFF);           // [64 rows][4 ngrp][2]
    float* bsum = (float*)(sm + BSUM_OFF);
    unsigned int* flag = (unsigned int*)(sm + FLAG_OFF);

    const uint32_t mbf[2] = {sbase + MBAR_OFF,      sbase + MBAR_OFF + 8};
    const uint32_t mbe[2] = {sbase + MBAR_OFF + 16, sbase + MBAR_OFF + 24};
    const uint32_t xsb    =  sbase + MBAR_OFF + 32;
    const uint32_t slot[2] = {sbase + WBUF_OFF, sbase + WBUF_OFF + CHUNK_B};

    b1s[tid] = b1[tid]; g1s[tid] = g1[tid]; be1s[tid] = be1[tid];
    b2s[tid] = b2[tid]; g2s[tid] = g2[tid]; be2s[tid] = be2[tid];
    w3s[tid] = W3[tid];

    if (tid == 0) {
        MBARRIER_INIT(mbf[0], 1); MBARRIER_INIT(mbf[1], 1);
        MBARRIER_INIT(mbe[0], 8); MBARRIER_INIT(mbe[1], 8);
        MBARRIER_INIT(xsb, 1);
    }
    __syncthreads();

    const int ntl = (NTILES - blockIdx.x + GRID - 1) / GRID;
    const int total_ch = ntl * NCHK;

    if (tid == 0) {
        // prime xs for first tile
        MBARRIER_EXPECT_TX(xsb, 11008u);
        bulk_g2s(sbase + A2H_OFF, (const char*)obs + (size_t)blockIdx.x * 9984, 9984u, xsb);
        bulk_g2s(sbase + A2H_OFF + 9984, (const char*)act + (size_t)blockIdx.x * 1024, 1024u, xsb);
        // prime weight chunks 0,1
        MBARRIER_EXPECT_TX(mbf[0], CHUNK_B);
        bulk_g2s(slot[0], g_wimg, CHUNK_B, mbf[0]);
        if (total_ch > 1) {
            MBARRIER_EXPECT_TX(mbf[1], CHUNK_B);
            bulk_g2s(slot[1], g_wimg + CHUNK_B, CHUNK_B, mbf[1]);
        }
    }

    const uint32_t ldsm_off = (uint32_t)((lane & 15) * ROWB + ((lane >> 4) << 3) * 2 + ngrp * 128);
    int fp0 = 0, fp1 = 0, ep0 = 0, ep1 = 0, xp = 0;
    int g = 0;    // global chunk cursor
    int lt = 0;

    for (int tile = blockIdx.x; tile < NTILES; tile += GRID, ++lt) {
        MBARRIER_WAIT_PARITY(xsb, xp); xp ^= 1;

        float c[2][8][4];
        #pragma unroll
        for (int mf = 0; mf < 2; mf++)
            #pragma unroll
            for (int nf = 0; nf < 8; nf++)
                { c[mf][nf][0]=0.f; c[mf][nf][1]=0.f; c[mf][nf][2]=0.f; c[mf][nf][3]=0.f; }

        // ---- GEMM1: 3 weight chunks (k48), A from xs ----
        for (int cc = 0; cc < 3; ++cc, ++g) {
            const int s = g & 1;
            MBARRIER_WAIT_PARITY(mbf[s], s ? fp1 : fp0);
            if (s) fp1 ^= 1; else fp0 ^= 1;

            uint32_t ah[2][4], al[2][4];
            #pragma unroll
            for (int mf = 0; mf < 2; mf++) {
                int r = mgrp * 32 + mf * 16 + qr;
                int c0 = cc * 16 + qc;
                float v[8];
                #pragma unroll
                for (int t = 0; t < 4; t++) {
                    int rr = r + (t & 1) * 8;
                    int cx = c0 + (t >> 1) * 8;
                    #pragma unroll
                    for (int e = 0; e < 2; e++) {
                        int ci = cx + e;
                        float vv = 0.f;
                        if (ci < SOBS) vv = xsO[rr * SOBS + ci];
                        else if (ci < SOBS + AACT) vv = xsA[rr * AACT + ci - SOBS];
                        v[t * 2 + e] = vv;
                    }
                }
                split2(v[0], v[1], ah[mf][0], al[mf][0]);
                split2(v[2], v[3], ah[mf][1], al[mf][1]);
                split2(v[4], v[5], ah[mf][2], al[mf][2]);
                split2(v[6], v[7], ah[mf][3], al[mf][3]);
            }

            uint32_t bb = slot[s] + ldsm_off;
            #pragma unroll
            for (int nf2 = 0; nf2 < 4; nf2++) {
                uint32_t h0, h1, h2, h3, l0, l1, l2, l3;
                ldsm4t(h0, h1, h2, h3, bb + nf2 * 32);
                ldsm4t(l0, l1, l2, l3, bb + PLANE_B + nf2 * 32);
                #pragma unroll
                for (int mf = 0; mf < 2; mf++) {
                    mma16816(c[mf][2*nf2],   ah[mf], h0, h1);
                    mma16816(c[mf][2*nf2+1], ah[mf], h2, h3);
                    mma16816(c[mf][2*nf2],   ah[mf], l0, l1);
                    mma16816(c[mf][2*nf2+1], ah[mf], l2, l3);
                    mma16816(c[mf][2*nf2],   al[mf], h0, h1);
                    mma16816(c[mf][2*nf2+1], al[mf], h2, h3);
                }
            }
            if (lane == 0) MBARRIER_ARRIVE(mbe[s]);
            if (tid == 0 && g + 2 < total_ch) {
                MBARRIER_WAIT_PARITY(mbe[s], s ? ep1 : ep0);
                if (s) ep1 ^= 1; else ep0 ^= 1;
                int cc2 = (g + 2) % NCHK;
                MBARRIER_EXPECT_TX(mbf[s], CHUNK_B);
                bulk_g2s(slot[s], g_wimg + cc2 * CHUNK_B, CHUNK_B, mbf[s]);
            }
        }

        // ---- LN1 (cross-4-warp stats) + ReLU -> A2 fragments ----
        {
            float st[4] = {0,0,0,0}, sq[4] = {0,0,0,0};
            #pragma unroll
            for (int mf = 0; mf < 2; mf++)
                #pragma unroll
                for (int nf = 0; nf < 8; nf++) {
                    float2 bb2 = *(const float2*)&b1s[ngrp * 64 + nf * 8 + qc];
                    float* cf = c[mf][nf];
                    cf[0] += bb2.x; cf[1] += bb2.y; cf[2] += bb2.x; cf[3] += bb2.y;
                    st[mf*2]   += cf[0] + cf[1];
                    sq[mf*2]    = fmaf(cf[0], cf[0], fmaf(cf[1], cf[1], sq[mf*2]));
                    st[mf*2+1] += cf[2] + cf[3];
                    sq[mf*2+1]  = fmaf(cf[2], cf[2], fmaf(cf[3], cf[3], sq[mf*2+1]));
                }
            #pragma unroll
            for (int i = 0; i < 4; i++) { st[i] = quad_sum(st[i]); sq[i] = quad_sum(sq[i]); }
            if ((lane & 3) == 0) {
                #pragma unroll
                for (int i = 0; i < 4; i++) {
                    int row = mgrp * 32 + (i >> 1) * 16 + (i & 1) * 8 + qr;
                    *(float2*)&lnx[(row * 4 + ngrp) * 2] = make_float2(st[i], sq[i]);
                }
            }
            __syncthreads();
            float mu[4], rs[4];
            #pragma unroll
            for (int i = 0; i < 4; i++) {
                int row = mgrp * 32 + (i >> 1) * 16 + (i & 1) * 8 + qr;
                float4 p0 = *(const float4*)&lnx[row * 8];
                float4 p1 = *(const float4*)&lnx[row * 8 + 4];
                float s = p0.x + p0.z + p1.x + p1.z;
                float q = p0.y + p0.w + p1.y + p1.w;
                float m = s * (1.f / HID);
                float var = q * (1.f / HID) - m * m + EPS;
                float r0 = rsqrtf(var); r0 = r0 * (1.5f - 0.5f * var * r0 * r0);
                mu[i] = m; rs[i] = r0;
            }
            #pragma unroll
            for (int mf = 0; mf < 2; mf++) {
                float m0 = mu[mf*2], r0 = rs[mf*2], m1 = mu[mf*2+1], r1 = rs[mf*2+1];
                int midx = mgrp * 2 + mf;
                #pragma unroll
                for (int j = 0; j < 4; j++) {
                    uint32_t hh[4], ll[4];
                    #pragma unroll
                    for (int t = 0; t < 2; t++) {
                        int nf = 2 * j + t;
                        int ncol = ngrp * 64 + nf * 8 + qc;
                        float2 gg = *(const float2*)&g1s[ncol];
                        float2 ee = *(const float2*)&be1s[ncol];
                        float* cf = c[mf][nf];
                        float v0 = fmaxf((cf[0] - m0) * r0 * gg.x + ee.x, 0.f);
                        float v1 = fmaxf((cf[1] - m0) * r0 * gg.y + ee.y, 0.f);
                        float v2 = fmaxf((cf[2] - m1) * r1 * gg.x + ee.x, 0.f);
                        float v3 = fmaxf((cf[3] - m1) * r1 * gg.y + ee.y, 0.f);
                        split2(v0, v1, hh[t*2],   ll[t*2]);
                        split2(v2, v3, hh[t*2+1], ll[t*2+1]);
                    }
                    int ki = ngrp * 4 + j;
                    uint32_t so = (uint32_t)(((midx * 16 + ki) * 32 + lane) * 16);
                    *(uint4*)(sm + A2H_OFF + so) = make_uint4(hh[0], hh[1], hh[2], hh[3]);
                    *(uint4*)(sm + A2L_OFF + so) = make_uint4(ll[0], ll[1], ll[2], ll[3]);
                }
            }
            __syncthreads();
        }

        // ---- GEMM2: 16 weight chunks (k256), A from A2 fragments ----
        #pragma unroll
        for (int mf = 0; mf < 2; mf++)
            #pragma unroll
            for (int nf = 0; nf < 8; nf++)
                { c[mf][nf][0]=0.f; c[mf][nf][1]=0.f; c[mf][nf][2]=0.f; c[mf][nf][3]=0.f; }

        for (int cc = 3; cc < NCHK; ++cc, ++g) {
            const int s = g & 1;
            MBARRIER_WAIT_PARITY(mbf[s], s ? fp1 : fp0);
            if (s) fp1 ^= 1; else fp0 ^= 1;

            const int ki = cc - 3;
            uint32_t ah[2][4], al[2][4];
            #pragma unroll
            for (int mf = 0; mf < 2; mf++) {
                int midx = mgrp * 2 + mf;
                uint32_t so = (uint32_t)(((midx * 16 + ki) * 32 + lane) * 16);
                uint4 a4 = *(const uint4*)(sm + A2H_OFF + so);
                uint4 b4 = *(const uint4*)(sm + A2L_OFF + so);
                ah[mf][0]=a4.x; ah[mf][1]=a4.y; ah[mf][2]=a4.z; ah[mf][3]=a4.w;
                al[mf][0]=b4.x; al[mf][1]=b4.y; al[mf][2]=b4.z; al[mf][3]=b4.w;
            }

            uint32_t bb = slot[s] + ldsm_off;
            #pragma unroll
            for (int nf2 = 0; nf2 < 4; nf2++) {
                uint32_t h0, h1, h2, h3, l0, l1, l2, l3;
                ldsm4t(h0, h1, h2, h3, bb + nf2 * 32);
                ldsm4t(l0, l1, l2, l3, bb + PLANE_B + nf2 * 32);
                #pragma unroll
                for (int mf = 0; mf < 2; mf++) {
                    mma16816(c[mf][2*nf2],   ah[mf], h0, h1);
                    mma16816(c[mf][2*nf2+1], ah[mf], h2, h3);
                    mma16816(c[mf][2*nf2],   ah[mf], l0, l1);
                    mma16816(c[mf][2*nf2+1], ah[mf], l2, l3);
                    mma16816(c[mf][2*nf2],   al[mf], h0, h1);
                    mma16816(c[mf][2*nf2+1], al[mf], h2, h3);
                }
            }
            if (lane == 0) MBARRIER_ARRIVE(mbe[s]);
            if (tid == 0 && g + 2 < total_ch) {
                MBARRIER_WAIT_PARITY(mbe[s], s ? ep1 : ep0);
                if (s) ep1 ^= 1; else ep0 ^= 1;
                int cc2 = (g + 2) % NCHK;
                MBARRIER_EXPECT_TX(mbf[s], CHUNK_B);
                bulk_g2s(slot[s], g_wimg + cc2 * CHUNK_B, CHUNK_B, mbf[s]);
            }
        }

        // ---- LN2 + ReLU + dot(W3) ----
        float rp = 0.f;
        {
            float st[4] = {0,0,0,0}, sq[4] = {0,0,0,0};
            #pragma unroll
            for (int mf = 0; mf < 2; mf++)
                #pragma unroll
                for (int nf = 0; nf < 8; nf++) {
                    float2 bb2 = *(const float2*)&b2s[ngrp * 64 + nf * 8 + qc];
                    float* cf = c[mf][nf];
                    cf[0] += bb2.x; cf[1] += bb2.y; cf[2] += bb2.x; cf[3] += bb2.y;
                    st[mf*2]   += cf[0] + cf[1];
                    sq[mf*2]    = fmaf(cf[0], cf[0], fmaf(cf[1], cf[1], sq[mf*2]));
                    st[mf*2+1] += cf[2] + cf[3];
                    sq[mf*2+1]  = fmaf(cf[2], cf[2], fmaf(cf[3], cf[3], sq[mf*2+1]));
                }
            #pragma unroll
            for (int i = 0; i < 4; i++) { st[i] = quad_sum(st[i]); sq[i] = quad_sum(sq[i]); }
            if ((lane & 3) == 0) {
                #pragma unroll
                for (int i = 0; i < 4; i++) {
                    int row = mgrp * 32 + (i >> 1) * 16 + (i & 1) * 8 + qr;
                    *(float2*)&lnx[(row * 4 + ngrp) * 2] = make_float2(st[i], sq[i]);
                }
            }
            __syncthreads();
            float mu[4], rs[4];
            #pragma unroll
            for (int i = 0; i < 4; i++) {
                int row = mgrp * 32 + (i >> 1) * 16 + (i & 1) * 8 + qr;
                float4 p0 = *(const float4*)&lnx[row * 8];
                float4 p1 = *(const float4*)&lnx[row * 8 + 4];
                float s = p0.x + p0.z + p1.x + p1.z;
                float q = p0.y + p0.w + p1.y + p1.w;
                float m = s * (1.f / HID);
                float var = q * (1.f / HID) - m * m + EPS;
                float r0 = rsqrtf(var); r0 = r0 * (1.5f - 0.5f * var * r0 * r0);
                mu[i] = m; rs[i] = r0;
            }
            #pragma unroll
            for (int mf = 0; mf < 2; mf++) {
                float m0 = mu[mf*2], r0 = rs[mf*2], m1 = mu[mf*2+1], r1 = rs[mf*2+1];
                #pragma unroll
                for (int nf = 0; nf < 8; nf++) {
                    int ncol = ngrp * 64 + nf * 8 + qc;
                    float2 gg = *(const float2*)&g2s[ncol];
                    float2 ee = *(const float2*)&be2s[ncol];
                    float2 ww = *(const float2*)&w3s[ncol];
                    float* cf = c[mf][nf];
                    float v0 = fmaxf((cf[0] - m0) * r0 * gg.x + ee.x, 0.f);
                    float v1 = fmaxf((cf[1] - m0) * r0 * gg.y + ee.y, 0.f);
                    float v2 = fmaxf((cf[2] - m1) * r1 * gg.x + ee.x, 0.f);
                    float v3 = fmaxf((cf[3] - m1) * r1 * gg.y + ee.y, 0.f);
                    rp = fmaf(v0, ww.x, rp); rp = fmaf(v1, ww.y, rp);
                    rp = fmaf(v2, ww.x, rp); rp = fmaf(v3, ww.y, rp);
                }
            }
        }
        rp = warp_sum(rp);
        if (lane == 0) bsum[warp] = rp;
        __syncthreads();
        if (tid == 0) {
            float t = 0.f;
            #pragma unroll
            for (int w = 0; w < 8; w++) t += bsum[w];
            g_partials[tile] = t;
        }
        __syncthreads();   // A2/xs region free, bsum consumed

        if (tid == 0 && lt + 1 < ntl) {
            size_t nt = (size_t)(tile + GRID);
            MBARRIER_EXPECT_TX(xsb, 11008u);
            bulk_g2s(sbase + A2H_OFF, (const char*)obs + nt * 9984, 9984u, xsb);
            bulk_g2s(sbase + A2H_OFF + 9984, (const char*)act + nt * 1024, 1024u, xsb);
        }
    }

    // ---- last-block deterministic reduction into out[] ----
    __threadfence();
    if (tid == 0) {
        unsigned int old = atomicAdd(&g_arrive, 1u);
        *flag = (old == GRID - 1) ? 1u : 0u;
    }
    __syncthreads();
    if (*flag) {
        __threadfence();
        float bb3 = b3[0];
        for (int b = tid; b < BATCH; b += THREADS) {
            float t = (float)TSEQ * bb3;
            #pragma unroll
            for (int i = 0; i < TPB; i++) t += __ldcg(&g_partials[b * TPB + i]);
            out[b] = t;
        }
        __syncthreads();
        if (tid == 0) { g_arrive = 0; __threadfence(); }
    }
}

extern "C" void kernel_launch(void* const* d_in, const int* in_sizes, int n_in,
                              void* d_out, int out_size)
{
    const float* obs = (const float*)d_in[0];
    const float* act = (const float*)d_in[1];
    const float* W1  = (const float*)d_in[2];
    const float* b1  = (const float*)d_in[3];
    const float* g1  = (const float*)d_in[4];
    const float* be1 = (const float*)d_in[5];
    const float* W2  = (const float*)d_in[6];
    const float* b2  = (const float*)d_in[7];
    const float* g2  = (const float*)d_in[8];
    const float* be2 = (const float*)d_in[9];
    const float* W3  = (const float*)d_in[10];
    const float* b3  = (const float*)d_in[11];

    prep_kernel<<<(NCHK * 16 * PITCH + 255) / 256, 256>>>(W1, W2);

    cudaFuncSetAttribute(fused_mma_kernel,
                         cudaFuncAttributeMaxDynamicSharedMemorySize, SMEM_DYN);
    fused_mma_kernel<<<GRID, THREADS, SMEM_DYN>>>(obs, act, b1, g1, be1, b2, g2, be2,
                                                  W3, b3, (float*)d_out);
}